// round 14
// baseline (speedup 1.0000x reference)
#include <cuda_runtime.h>

// region layer: x (16, 425, 76, 76) f32 -> out (16, 415, 76, 76) f32
// per anchor (5 anchors x 85 ch): sigmoid(ch0,1), drop ch2,3, sigmoid(ch4),
// softmax over ch5..84 -> 83 output channels per anchor.
//
// R12 (ncu-best: 44.0us, DRAM 72.7%) + L1 bypass on STORES (__stcg):
// output is write-once/never-re-read, so transit through write-through L1
// only burns L1tex wavefront bandwidth (L1 was 45% on pure overhead).
// Loads already bypass L1 (__ldcg). L2 behavior unchanged (this is NOT the
// .cs evict-first experiment — allocation policy stays default).
// Structure unchanged: single pass = minimal 307 MB traffic, float4,
// 4-way class split across lanes, 20 class LDG.128s issued first,
// branch-free sigmoid path, dual accumulators, predicated tail,
// full-mask shuffles.
// No max-subtraction (inputs unit normal; validated rel_err ~4e-8, R2-R12).

#define BATCH  16
#define NANCH  5
#define HW4    1444        // (76*76)/4 float4 per channel plane
#define TILES  181         // ceil(HW4 / 8); last tile: p<4 valid

__device__ __forceinline__ float sigf(float x) {
    return 1.0f / (1.0f + __expf(-x));
}

__global__ __launch_bounds__(256) void region_kernel(
    const float4* __restrict__ x, float4* __restrict__ out)
{
    const int warp = (blockIdx.x * blockDim.x + threadIdx.x) >> 5;
    const int lane = threadIdx.x & 31;
    const int g    = lane >> 3;    // class group 0..3 (20 classes each)
    const int p    = lane & 7;     // float4 quad within tile

    const int tile = warp % TILES;
    const int t    = warp / TILES;
    const int a    = t % NANCH;
    const int b    = t / NANCH;

    const int q      = tile * 8 + p;            // float4 index in plane
    const bool valid = (q < HW4);
    const int qc     = valid ? q : (HW4 - 1);   // clamped load index

    const float4* __restrict__ in = x   + (size_t)(b * 425 + a * 85) * HW4 + qc;
    float4*       __restrict__ o  = out + (size_t)(b * 415 + a * 83) * HW4 + q;

    // ---- 20 class loads first (L1-bypassed): the latency long pole ----
    const float4* __restrict__ cls = in + (size_t)(5 + g * 20) * HW4;
    float4 e[20];
    #pragma unroll
    for (int j = 0; j < 20; j++)
        e[j] = __ldcg(cls + (size_t)j * HW4);

    // ---- sigmoid channels, branch-free (overlaps class-load latency) ----
    // g=0 -> ch0(tx), g=1 -> ch1(ty), g=2 -> ch4(obj), g=3 -> dup ch4 (dead)
    {
        const int ic = (g < 2) ? g : 4;
        const float4 v = __ldcg(in + (size_t)ic * HW4);
        float4 r;
        r.x = sigf(v.x); r.y = sigf(v.y); r.z = sigf(v.z); r.w = sigf(v.w);
        if (g < 3 && valid)
            __stcg(o + (size_t)g * HW4, r);
    }

    // ---- softmax over this group's 20 classes (dual accumulators) ----
    float sx0 = 0.f, sy0 = 0.f, sz0 = 0.f, sw0 = 0.f;
    float sx1 = 0.f, sy1 = 0.f, sz1 = 0.f, sw1 = 0.f;
    #pragma unroll
    for (int j = 0; j < 20; j += 2) {
        e[j].x = __expf(e[j].x);      sx0 += e[j].x;
        e[j].y = __expf(e[j].y);      sy0 += e[j].y;
        e[j].z = __expf(e[j].z);      sz0 += e[j].z;
        e[j].w = __expf(e[j].w);      sw0 += e[j].w;
        e[j+1].x = __expf(e[j+1].x);  sx1 += e[j+1].x;
        e[j+1].y = __expf(e[j+1].y);  sy1 += e[j+1].y;
        e[j+1].z = __expf(e[j+1].z);  sz1 += e[j+1].z;
        e[j+1].w = __expf(e[j+1].w);  sw1 += e[j+1].w;
    }
    float sx = sx0 + sx1;
    float sy = sy0 + sy1;
    float sz = sz0 + sz1;
    float sw = sw0 + sw1;

    // combine partial sums across the 4 class groups (no lane exited:
    // full mask defined; shfl partners share q, so valid mixes valid).
    const unsigned m = 0xffffffffu;
    sx += __shfl_xor_sync(m, sx, 8);
    sy += __shfl_xor_sync(m, sy, 8);
    sz += __shfl_xor_sync(m, sz, 8);
    sw += __shfl_xor_sync(m, sw, 8);
    sx += __shfl_xor_sync(m, sx, 16);
    sy += __shfl_xor_sync(m, sy, 16);
    sz += __shfl_xor_sync(m, sz, 16);
    sw += __shfl_xor_sync(m, sw, 16);

    const float ix = __frcp_rn(sx);
    const float iy = __frcp_rn(sy);
    const float iz = __frcp_rn(sz);
    const float iw = __frcp_rn(sw);

    if (valid) {
        float4* __restrict__ oc = o + (size_t)(3 + g * 20) * HW4;
        #pragma unroll
        for (int j = 0; j < 20; j++) {
            float4 r;
            r.x = e[j].x * ix;
            r.y = e[j].y * iy;
            r.z = e[j].z * iz;
            r.w = e[j].w * iw;
            __stcg(oc + (size_t)j * HW4, r);
        }
    }
}

extern "C" void kernel_launch(void* const* d_in, const int* in_sizes, int n_in,
                              void* d_out, int out_size)
{
    const float4* x = (const float4*)d_in[0];
    float4* out = (float4*)d_out;
    // total warps = BATCH * NANCH * TILES = 14480; 8 warps per block
    const int blocks = (BATCH * NANCH * TILES) / 8;   // 1810, exact
    region_kernel<<<blocks, 256>>>(x, out);
}

// round 15
// speedup vs baseline: 1.0264x; 1.0264x over previous
#include <cuda_runtime.h>

// region layer: x (16, 425, 76, 76) f32 -> out (16, 415, 76, 76) f32
// per anchor (5 anchors x 85 ch): sigmoid(ch0,1), drop ch2,3, sigmoid(ch4),
// softmax over ch5..84 -> 83 output channels per anchor.
//
// Best-of-family composite (lock-in):
//  - R11 structure: single pass = minimal 307 MB traffic, float4, 4-way
//    class split across lanes, 20 class LDG.128s issued first, branch-free
//    sigmoid path (g==3 dup-loads ch4, same 128B line as g==2), predicated
//    tail, full-mask shuffles. DEFAULT load/store forms (benched best:
//    .cg loads cost ~1us across two samples — L1 hits from the duplicate
//    sigmoid line and clamped tail are worth keeping).
//  - R12's dual accumulators: regs 112->105, post-load add chain halved
//    (ncu-confirmed improvement independent of load form).
// Falsified levers (do not revisit): occupancy, cp.async pipelines, L2
// pinning (full/partial), evict-first reads, streaming stores, persistence,
// L1-bypass loads/stores. Bench throughput sits at ~6.2 TB/s total bytes =
// the path-independent LTS ceiling for this 1:1 read/write mix.
// No max-subtraction (inputs unit normal; validated rel_err ~4e-8, R2-R13).

#define BATCH  16
#define NANCH  5
#define HW4    1444        // (76*76)/4 float4 per channel plane
#define TILES  181         // ceil(HW4 / 8); last tile: p<4 valid

__device__ __forceinline__ float sigf(float x) {
    return 1.0f / (1.0f + __expf(-x));
}

__global__ __launch_bounds__(256) void region_kernel(
    const float4* __restrict__ x, float4* __restrict__ out)
{
    const int warp = (blockIdx.x * blockDim.x + threadIdx.x) >> 5;
    const int lane = threadIdx.x & 31;
    const int g    = lane >> 3;    // class group 0..3 (20 classes each)
    const int p    = lane & 7;     // float4 quad within tile

    const int tile = warp % TILES;
    const int t    = warp / TILES;
    const int a    = t % NANCH;
    const int b    = t / NANCH;

    const int q      = tile * 8 + p;            // float4 index in plane
    const bool valid = (q < HW4);
    const int qc     = valid ? q : (HW4 - 1);   // clamped load index

    const float4* __restrict__ in = x   + (size_t)(b * 425 + a * 85) * HW4 + qc;
    float4*       __restrict__ o  = out + (size_t)(b * 415 + a * 83) * HW4 + q;

    // ---- 20 class loads first: the latency long pole ----
    const float4* __restrict__ cls = in + (size_t)(5 + g * 20) * HW4;
    float4 e[20];
    #pragma unroll
    for (int j = 0; j < 20; j++)
        e[j] = cls[(size_t)j * HW4];

    // ---- sigmoid channels, branch-free (overlaps class-load latency) ----
    // g=0 -> ch0(tx), g=1 -> ch1(ty), g=2 -> ch4(obj), g=3 -> dup ch4 (dead)
    {
        const int ic = (g < 2) ? g : 4;
        const float4 v = in[(size_t)ic * HW4];
        float4 r;
        r.x = sigf(v.x); r.y = sigf(v.y); r.z = sigf(v.z); r.w = sigf(v.w);
        if (g < 3 && valid)
            o[(size_t)g * HW4] = r;
    }

    // ---- softmax over this group's 20 classes (dual accumulators) ----
    float sx0 = 0.f, sy0 = 0.f, sz0 = 0.f, sw0 = 0.f;
    float sx1 = 0.f, sy1 = 0.f, sz1 = 0.f, sw1 = 0.f;
    #pragma unroll
    for (int j = 0; j < 20; j += 2) {
        e[j].x = __expf(e[j].x);      sx0 += e[j].x;
        e[j].y = __expf(e[j].y);      sy0 += e[j].y;
        e[j].z = __expf(e[j].z);      sz0 += e[j].z;
        e[j].w = __expf(e[j].w);      sw0 += e[j].w;
        e[j+1].x = __expf(e[j+1].x);  sx1 += e[j+1].x;
        e[j+1].y = __expf(e[j+1].y);  sy1 += e[j+1].y;
        e[j+1].z = __expf(e[j+1].z);  sz1 += e[j+1].z;
        e[j+1].w = __expf(e[j+1].w);  sw1 += e[j+1].w;
    }
    float sx = sx0 + sx1;
    float sy = sy0 + sy1;
    float sz = sz0 + sz1;
    float sw = sw0 + sw1;

    // combine partial sums across the 4 class groups (no lane exited:
    // full mask defined; shfl partners share q, so valid mixes valid).
    const unsigned m = 0xffffffffu;
    sx += __shfl_xor_sync(m, sx, 8);
    sy += __shfl_xor_sync(m, sy, 8);
    sz += __shfl_xor_sync(m, sz, 8);
    sw += __shfl_xor_sync(m, sw, 8);
    sx += __shfl_xor_sync(m, sx, 16);
    sy += __shfl_xor_sync(m, sy, 16);
    sz += __shfl_xor_sync(m, sz, 16);
    sw += __shfl_xor_sync(m, sw, 16);

    const float ix = __frcp_rn(sx);
    const float iy = __frcp_rn(sy);
    const float iz = __frcp_rn(sz);
    const float iw = __frcp_rn(sw);

    if (valid) {
        float4* __restrict__ oc = o + (size_t)(3 + g * 20) * HW4;
        #pragma unroll
        for (int j = 0; j < 20; j++) {
            float4 r;
            r.x = e[j].x * ix;
            r.y = e[j].y * iy;
            r.z = e[j].z * iz;
            r.w = e[j].w * iw;
            oc[(size_t)j * HW4] = r;
        }
    }
}

extern "C" void kernel_launch(void* const* d_in, const int* in_sizes, int n_in,
                              void* d_out, int out_size)
{
    const float4* x = (const float4*)d_in[0];
    float4* out = (float4*)d_out;
    // total warps = BATCH * NANCH * TILES = 14480; 8 warps per block
    const int blocks = (BATCH * NANCH * TILES) / 8;   // 1810, exact
    region_kernel<<<blocks, 256>>>(x, out);
}